// round 12
// baseline (speedup 1.0000x reference)
#include <cuda_runtime.h>
#include <cuda_bf16.h>

// Problem constants (fixed shapes: x = (8,3,1024,1024) fp32, patch_size=24, stride=16)
namespace {
constexpr int Hh  = 1024;
constexpr int Ww  = 1024;
constexpr int Bb  = 8;
constexpr int Cc  = 3;
constexpr int PS  = 24;   // patch size
constexpr int ST  = 16;   // stride
constexpr int Mm  = 4;    // (PS - ST) / 2 reflect pad
constexpr int NH  = 64;   // 1024 / 16
constexpr int NW  = 64;
constexpr int ROWLEN = Ww + 2 * Mm;          // 1032 padded row
constexpr int THREADS = 384;
constexpr int OUT_F4_PER_PR = (NW * PS * Cc) / 4;  // 64*24*3/4 = 1152 float4 per (b,i,r)
constexpr int PATCH_F4 = (PS * PS * Cc) / 4;       // 432 float4 per patch
}

// One block handles one (b, i, r): a single padded source row feeding all 64
// patches in that patch-row at within-patch row r.
//  - load x[b, ch, reflect(i*16+r-4), :] for ch=0..2 into smem (float4, coalesced)
//  - fix reflect halo columns from global
//  - emit 1152 float4 of output, each float4 = 4 consecutive (c,ch) interleaved
//    values of one patch (never spans a patch: 72 % 4 == 0 within j)
__global__ __launch_bounds__(THREADS)
void patcher_kernel(const float* __restrict__ x, float4* __restrict__ out)
{
    __shared__ float srow[Cc][ROWLEN];

    const int r = blockIdx.x;   // 0..23  within-patch row
    const int i = blockIdx.y;   // 0..63  patch row
    const int b = blockIdx.z;   // 0..7   batch
    const int t = threadIdx.x;

    // source row with reflect padding (reflect w/o edge repeat, jnp default)
    int v = i * ST + r - Mm;
    v = (v < 0) ? -v : v;
    v = (v > Hh - 1) ? 2 * (Hh - 1) - v : v;

    // ---- cooperative row load: 3 channels x 256 float4 = 768 loads ----
    #pragma unroll
    for (int it = 0; it < 2; ++it) {
        int idx = t + it * THREADS;            // 0..767
        int ch  = idx >> 8;                    // /256
        int g   = idx & 255;
        const float4* src = reinterpret_cast<const float4*>(
            x + (((size_t)(b * Cc + ch)) * Hh + (size_t)v) * Ww);
        float4 val = src[g];
        // smem offset (Mm + 4g) floats = 16(g+1) bytes -> 16B aligned
        *reinterpret_cast<float4*>(&srow[ch][Mm + 4 * g]) = val;
    }

    // ---- reflect halo columns (4 left + 4 right per channel) ----
    if (t < Cc * 8) {
        int ch = t >> 3;
        int p  = t & 7;
        const float* rowp = x + (((size_t)(b * Cc + ch)) * Hh + (size_t)v) * Ww;
        if (p < 4) {
            // smem s = 3-p  <=>  orig col -(p+1) -> reflect -> col p+1
            srow[ch][3 - p] = rowp[p + 1];
        } else {
            int k = p - 3;  // 1..4 ; smem s = 4+1023+k <=> orig 1023+k -> 1023-k
            srow[ch][Mm + (Ww - 1) + k] = rowp[(Ww - 1) - k];
        }
    }
    __syncthreads();

    // ---- emit: out[((b*64+i)*64 + j)*432 + r*18 + t18] (float4 units) ----
    const size_t base0 = ((size_t)(b * NH + i) * NW) * PATCH_F4 + (size_t)r * 18;

    #pragma unroll
    for (int it = 0; it < 3; ++it) {
        int q   = t + it * THREADS;     // 0..1151
        int j   = q / 18;               // patch column 0..63
        int t18 = q - j * 18;           // float4 index inside this (p, r) run
        int rem = 4 * t18;              // element index within 72-float run
        int scb = j * ST;               // smem col base: orig j*16+c-4, +Mm pad

        float4 val;
        { int e = rem;     int c = e / 3, ch = e - 3 * c; val.x = srow[ch][scb + c]; }
        { int e = rem + 1; int c = e / 3, ch = e - 3 * c; val.y = srow[ch][scb + c]; }
        { int e = rem + 2; int c = e / 3, ch = e - 3 * c; val.z = srow[ch][scb + c]; }
        { int e = rem + 3; int c = e / 3, ch = e - 3 * c; val.w = srow[ch][scb + c]; }

        out[base0 + (size_t)j * PATCH_F4 + t18] = val;
    }
}

// Trailing (nH, nW) = (64, 64) if the harness appends them to the output.
__global__ void patcher_extras(float* __restrict__ out, int n)
{
    int t = threadIdx.x;
    if (t < n) out[t] = 64.0f;
}

extern "C" void kernel_launch(void* const* d_in, const int* in_sizes, int n_in,
                              void* d_out, int out_size)
{
    const float* x = (const float*)d_in[0];
    float* out = (float*)d_out;

    dim3 grid(PS, NH, Bb);  // (24, 64, 8) = 12288 blocks
    patcher_kernel<<<grid, THREADS>>>(x, reinterpret_cast<float4*>(out));

    const long long main_sz = (long long)Bb * NH * NW * PS * PS * Cc;  // 56,623,104
    long long extra = (long long)out_size - main_sz;
    if (extra > 0) {
        patcher_extras<<<1, 64>>>(out + main_sz, (int)extra);
    }
}

// round 13
// speedup vs baseline: 1.0595x; 1.0595x over previous
#include <cuda_runtime.h>
#include <cuda_bf16.h>

// Problem constants (fixed shapes: x = (8,3,1024,1024) fp32, patch_size=24, stride=16)
namespace {
constexpr int Hh  = 1024;
constexpr int Ww  = 1024;
constexpr int Bb  = 8;
constexpr int Cc  = 3;
constexpr int PS  = 24;   // patch size
constexpr int ST  = 16;   // stride
constexpr int Mm  = 4;    // (PS - ST) / 2 reflect pad
constexpr int NH  = 64;   // 1024 / 16
constexpr int NW  = 64;
constexpr int ROWLEN = Ww + 2 * Mm;              // 1032 padded row
constexpr int THREADS = 384;
constexpr int PATCH_F4 = (PS * PS * Cc) / 4;     // 432 float4 per patch
constexpr long long MAIN_SZ = (long long)Bb * NH * NW * PS * PS * Cc; // 56,623,104
}

// One block handles one (b, i, r): a single padded source row feeding all 64
// patches in that patch-row at within-patch row r.
//  - load x[b, ch, reflect(i*16+r-4), :] for ch=0..2 into smem (float4, coalesced)
//  - fix reflect halo columns from global
//  - emit 1152 float4 of output via __stcs (streaming: output is never re-read,
//    keep the input resident in L2 instead)
// Block (0,0,0) additionally writes the trailing (nH, nW) scalars, replacing
// the old separate patcher_extras launch (~3.5us of graph-serialized overhead).
__global__ __launch_bounds__(THREADS)
void patcher_kernel(const float* __restrict__ x, float4* __restrict__ out,
                    float* __restrict__ extras, int n_extra)
{
    __shared__ float srow[Cc][ROWLEN];

    const int r = blockIdx.x;   // 0..23  within-patch row
    const int i = blockIdx.y;   // 0..63  patch row
    const int b = blockIdx.z;   // 0..7   batch
    const int t = threadIdx.x;

    // fused trailing (nH, nW) write — one designated block, tiny
    if (r == 0 && i == 0 && b == 0 && t < n_extra) {
        extras[t] = 64.0f;   // nH = nW = 64
    }

    // source row with reflect padding (reflect w/o edge repeat, jnp default)
    int v = i * ST + r - Mm;
    v = (v < 0) ? -v : v;
    v = (v > Hh - 1) ? 2 * (Hh - 1) - v : v;

    // ---- cooperative row load: 3 channels x 256 float4 = 768 loads ----
    #pragma unroll
    for (int it = 0; it < 2; ++it) {
        int idx = t + it * THREADS;            // 0..767
        int ch  = idx >> 8;                    // /256
        int g   = idx & 255;
        const float4* src = reinterpret_cast<const float4*>(
            x + (((size_t)(b * Cc + ch)) * Hh + (size_t)v) * Ww);
        float4 val = src[g];
        // smem offset (Mm + 4g) floats = 16(g+1) bytes -> 16B aligned
        *reinterpret_cast<float4*>(&srow[ch][Mm + 4 * g]) = val;
    }

    // ---- reflect halo columns (4 left + 4 right per channel) ----
    if (t < Cc * 8) {
        int ch = t >> 3;
        int p  = t & 7;
        const float* rowp = x + (((size_t)(b * Cc + ch)) * Hh + (size_t)v) * Ww;
        if (p < 4) {
            // smem s = 3-p  <=>  orig col -(p+1) -> reflect -> col p+1
            srow[ch][3 - p] = rowp[p + 1];
        } else {
            int k = p - 3;  // 1..4 ; smem s = 4+1023+k <=> orig 1023+k -> 1023-k
            srow[ch][Mm + (Ww - 1) + k] = rowp[(Ww - 1) - k];
        }
    }
    __syncthreads();

    // ---- emit: out[((b*64+i)*64 + j)*432 + r*18 + t18] (float4 units) ----
    const size_t base0 = ((size_t)(b * NH + i) * NW) * PATCH_F4 + (size_t)r * 18;

    #pragma unroll
    for (int it = 0; it < 3; ++it) {
        int q   = t + it * THREADS;     // 0..1151
        int j   = q / 18;               // patch column 0..63
        int t18 = q - j * 18;           // float4 index inside this (p, r) run
        int rem = 4 * t18;              // element index within 72-float run
        int scb = j * ST;               // smem col base: orig j*16+c-4, +Mm pad

        float4 val;
        { int e = rem;     int c = e / 3, ch = e - 3 * c; val.x = srow[ch][scb + c]; }
        { int e = rem + 1; int c = e / 3, ch = e - 3 * c; val.y = srow[ch][scb + c]; }
        { int e = rem + 2; int c = e / 3, ch = e - 3 * c; val.z = srow[ch][scb + c]; }
        { int e = rem + 3; int c = e / 3, ch = e - 3 * c; val.w = srow[ch][scb + c]; }

        // streaming store: output is write-once, don't let it evict the input
        // (100 MB input fits in the 126 MB L2; rows are re-read ~1.5x)
        __stcs(&out[base0 + (size_t)j * PATCH_F4 + t18], val);
    }
}

extern "C" void kernel_launch(void* const* d_in, const int* in_sizes, int n_in,
                              void* d_out, int out_size)
{
    const float* x = (const float*)d_in[0];
    float* out = (float*)d_out;

    long long extra = (long long)out_size - MAIN_SZ;
    int n_extra = extra > 0 ? (int)extra : 0;

    dim3 grid(PS, NH, Bb);  // (24, 64, 8) = 12288 blocks
    patcher_kernel<<<grid, THREADS>>>(x, reinterpret_cast<float4*>(out),
                                      out + MAIN_SZ, n_extra);
}